// round 2
// baseline (speedup 1.0000x reference)
#include <cuda_runtime.h>
#include <math.h>

// B=131072, D=512, N=1.
// loss_b = log1p(exp((dot(img,neg) - dot(img,pos)) / 50)); output = mean_b loss_b.
// Single fused kernel: per-block partial via plain STG, last block reduces.

#define B_TOTAL 131072
#define D_F4 128              // 512 floats = 128 float4 per row
#define WARPS_PER_BLOCK 8
#define THREADS 256
#define NBLOCKS (B_TOTAL / WARPS_PER_BLOCK)   // 16384

__device__ __align__(16) float g_partial[NBLOCKS];
__device__ unsigned int g_ticket = 0;   // always returns to 0 (last block resets)

__global__ __launch_bounds__(THREADS) void loss_fused_kernel(
    const float4* __restrict__ img,
    const float4* __restrict__ pos,
    const float4* __restrict__ neg,
    float* __restrict__ out)
{
    const int wid  = threadIdx.x >> 5;
    const int lane = threadIdx.x & 31;
    const size_t row  = (size_t)blockIdx.x * WARPS_PER_BLOCK + wid;
    const size_t base = row * D_F4 + lane;

    float dp = 0.0f, dn = 0.0f;
#pragma unroll
    for (int i = 0; i < 4; i++) {
        const float4 a = __ldg(img + base + i * 32);
        const float4 p = __ldg(pos + base + i * 32);
        const float4 n = __ldg(neg + base + i * 32);
        dp += a.x * p.x + a.y * p.y + a.z * p.z + a.w * p.w;
        dn += a.x * n.x + a.y * n.y + a.z * n.z + a.w * n.w;
    }

#pragma unroll
    for (int off = 16; off; off >>= 1) {
        dp += __shfl_xor_sync(0xffffffffu, dp, off);
        dn += __shfl_xor_sync(0xffffffffu, dn, off);
    }

    __shared__ float s_loss[WARPS_PER_BLOCK];
    __shared__ bool  s_last;
    if (lane == 0) {
        // -log(ep/(ep+en)) == log1p(exp((dn-dp)/50))
        s_loss[wid] = log1pf(expf((dn - dp) * 0.02f));
    }
    __syncthreads();

    if (threadIdx.x == 0) {
        float sum = 0.0f;
#pragma unroll
        for (int i = 0; i < WARPS_PER_BLOCK; i++) sum += s_loss[i];
        g_partial[blockIdx.x] = sum;
        __threadfence();                      // publish partial before ticket
        unsigned int t = atomicAdd(&g_ticket, 1u);
        s_last = (t == NBLOCKS - 1);
    }
    __syncthreads();

    if (s_last) {
        // Last block: all partials are globally visible (fence+atomic order).
        __threadfence();
        const float4* p4 = (const float4*)g_partial;   // 4096 float4
        float acc = 0.0f;
        for (int i = threadIdx.x; i < NBLOCKS / 4; i += THREADS) {
            float4 v = p4[i];
            acc += v.x + v.y + v.z + v.w;
        }
#pragma unroll
        for (int off = 16; off; off >>= 1)
            acc += __shfl_xor_sync(0xffffffffu, acc, off);

        __shared__ float s_fin[WARPS_PER_BLOCK];
        if (lane == 0) s_fin[wid] = acc;
        __syncthreads();
        if (threadIdx.x == 0) {
            float tot = 0.0f;
#pragma unroll
            for (int i = 0; i < WARPS_PER_BLOCK; i++) tot += s_fin[i];
            out[0] = tot / (float)B_TOTAL;
            g_ticket = 0;                     // reset for next graph replay
        }
    }
}

extern "C" void kernel_launch(void* const* d_in, const int* in_sizes, int n_in,
                              void* d_out, int out_size) {
    (void)in_sizes; (void)n_in; (void)out_size;
    const float4* img = (const float4*)d_in[0];
    const float4* pos = (const float4*)d_in[1];
    const float4* neg = (const float4*)d_in[2];
    float* out = (float*)d_out;

    loss_fused_kernel<<<NBLOCKS, THREADS>>>(img, pos, neg, out);
}

// round 6
// speedup vs baseline: 1.0562x; 1.0562x over previous
#include <cuda_runtime.h>
#include <math.h>

// B=131072, D=512, N=1.
// loss_b = log1p(exp((dot(img,neg) - dot(img,pos)) / 50)); output = mean_b loss_b.
// Two kernels: main (plain STG per-block partial, no atomics/fences) + finalize.

#define B_TOTAL 131072
#define D_F4 128              // 512 floats = 128 float4 per row
#define WARPS_PER_BLOCK 8
#define THREADS 256
#define NBLOCKS (B_TOTAL / WARPS_PER_BLOCK)   // 16384

__device__ __align__(16) float g_partial[NBLOCKS];

__global__ __launch_bounds__(THREADS) void loss_main_kernel(
    const float4* __restrict__ img,
    const float4* __restrict__ pos,
    const float4* __restrict__ neg)
{
    const int wid  = threadIdx.x >> 5;
    const int lane = threadIdx.x & 31;
    const size_t row  = (size_t)blockIdx.x * WARPS_PER_BLOCK + wid;
    const size_t base = row * D_F4 + lane;

    float dp = 0.0f, dn = 0.0f;
#pragma unroll
    for (int i = 0; i < 4; i++) {
        const float4 a = __ldg(img + base + i * 32);
        const float4 p = __ldg(pos + base + i * 32);
        const float4 n = __ldg(neg + base + i * 32);
        dp += a.x * p.x + a.y * p.y + a.z * p.z + a.w * p.w;
        dn += a.x * n.x + a.y * n.y + a.z * n.z + a.w * n.w;
    }

#pragma unroll
    for (int off = 16; off; off >>= 1) {
        dp += __shfl_xor_sync(0xffffffffu, dp, off);
        dn += __shfl_xor_sync(0xffffffffu, dn, off);
    }

    __shared__ float s_loss[WARPS_PER_BLOCK];
    if (lane == 0) {
        // -log(ep/(ep+en)) == log1p(exp((dn-dp)/50))
        s_loss[wid] = log1pf(expf((dn - dp) * 0.02f));
    }
    __syncthreads();

    if (threadIdx.x == 0) {
        float sum = 0.0f;
#pragma unroll
        for (int i = 0; i < WARPS_PER_BLOCK; i++) sum += s_loss[i];
        g_partial[blockIdx.x] = sum;          // plain STG: no zero pass needed
    }
}

__global__ __launch_bounds__(THREADS) void finalize_kernel(float* __restrict__ out) {
    const int wid  = threadIdx.x >> 5;
    const int lane = threadIdx.x & 31;

    const float4* p4 = (const float4*)g_partial;   // 4096 float4
    float acc = 0.0f;
#pragma unroll
    for (int i = 0; i < (NBLOCKS / 4) / THREADS; i++) {   // 16 iters
        float4 v = p4[threadIdx.x + i * THREADS];
        acc += v.x + v.y + v.z + v.w;
    }
#pragma unroll
    for (int off = 16; off; off >>= 1)
        acc += __shfl_xor_sync(0xffffffffu, acc, off);

    __shared__ float s_fin[WARPS_PER_BLOCK];
    if (lane == 0) s_fin[wid] = acc;
    __syncthreads();
    if (threadIdx.x == 0) {
        float tot = 0.0f;
#pragma unroll
        for (int i = 0; i < WARPS_PER_BLOCK; i++) tot += s_fin[i];
        out[0] = tot / (float)B_TOTAL;
    }
}

extern "C" void kernel_launch(void* const* d_in, const int* in_sizes, int n_in,
                              void* d_out, int out_size) {
    (void)in_sizes; (void)n_in; (void)out_size;
    const float4* img = (const float4*)d_in[0];
    const float4* pos = (const float4*)d_in[1];
    const float4* neg = (const float4*)d_in[2];
    float* out = (float*)d_out;

    loss_main_kernel<<<NBLOCKS, THREADS>>>(img, pos, neg);
    finalize_kernel<<<1, THREADS>>>(out);
}